// round 15
// baseline (speedup 1.0000x reference)
#include <cuda_runtime.h>

#define NS 8
#define NC 128
#define KT 32
#define KF 16
#define FREQ 256
#define NFW 15
#define THR 15.0f
#define LPRE 431
#define NPOT 6400
#define MARGIN 0.05f
#define NCAND 16
#define NT 1024

#define TP 33
#define RTP 433
#define RT_OFF  14224        /* tile = 431*33 = 14223 */
#define S_OFF   21152        /* Rt = 16*433 = 6928 */
#define V_OFF   27552
#define RT2_OFF 33952
#define XP_OFF  40880        /* xpatch[16][512] */
#define SMEM_F  49072        /* 196,288 bytes */

__device__ unsigned g_poolw[NS * NFW * 4];
__device__ unsigned g_done;

__global__ __launch_bounds__(NT, 1)
void spyke_kernel(const float* __restrict__ X, const float* __restrict__ W,
                  int* __restrict__ out)
{
    extern __shared__ float sm[];
    float* tile   = sm;
    float* Rt     = sm + RT_OFF;     /* transposed row sums [16][433] */
    float* Sarr   = sm + S_OFF;
    float* Varr   = sm + V_OFF;
    float* Rt2    = sm + RT2_OFF;
    float* xpatch = sm + XP_OFF;

    __shared__ unsigned long long s_cand[NCAND];
    __shared__ int s_p[NCAND];
    __shared__ unsigned s_pool[4];
    __shared__ int s_sig_i, s_rcnt, s_qhead, s_last, s_any, s_key0, s_key1;
    __shared__ int s_rem[NC];

    const int s = blockIdx.x / NFW, fwin = blockIdx.x % NFW;
    const int tid = threadIdx.x, sec = s * 400, col0 = fwin * 16;
    const int lane = tid & 31, wid = tid >> 5;

    if (tid < NCAND) s_cand[tid] = 0ULL;
    if (tid < 4) s_pool[tid] = 0u;
    if (tid == 0) { s_rcnt = 0; s_sig_i = 0; s_qhead = 0; }

    const float* Wsec = W + (size_t)s * NC * 512;

    // ---- prefetch W section into L2 ----
    for (int i = tid; i < 2048; i += NT)
        asm volatile("prefetch.global.L2 [%0];" :: "l"(Wsec + i * 32));

    // ---- fused stage + row-window-sums (warp per row, shuffle prefix scan) ----
    for (int r = wid; r < LPRE; r += 32) {
        float x = 0.f;
        if (lane < 31) x = X[(size_t)(sec + r) * FREQ + col0 + lane];
        if (lane < 31) tile[r * TP + lane] = x;
        float p = x;
        #pragma unroll
        for (int d = 1; d < 32; d <<= 1) {
            float v = __shfl_up_sync(~0u, p, d);
            if (lane >= d) p += v;
        }
        float phi = __shfl_down_sync(~0u, p, 15);   /* lane f: P[f+15] */
        float plo = __shfl_up_sync(~0u, p, 1);      /* lane f: P[f-1]  */
        if (lane < 16) Rt[lane * RTP + r] = phi - (lane ? plo : 0.f);
    }
    __syncthreads();

    // ---- column sliding over kt-window of 32 (stride-1 reads, 800 thr) ----
    if (tid < 800) {
        int f = tid & 15, t0 = (tid >> 4) * 8;
        const float* Rf = Rt + f * RTP;
        float a = 0.f;
        #pragma unroll 8
        for (int k = 0; k < 32; ++k) a += Rf[t0 + k];
        unsigned long long lkey[2] = {0ULL, 0ULL};
        int reg0 = t0 / 25;
        #pragma unroll
        for (int t = t0; t < t0 + 8; ++t) {
            int p = t*16 + f;
            Sarr[p] = a;
            unsigned long long key =
                ((unsigned long long)__float_as_uint(a) << 13) | (unsigned)p;
            int ri = (t / 25) - reg0;
            if (key > lkey[ri]) lkey[ri] = key;
            if (t <= 398) a += Rf[t + 32] - Rf[t];
        }
        atomicMax(&s_cand[reg0], lkey[0]);
        if (lkey[1] && reg0 + 1 < NCAND) atomicMax(&s_cand[reg0 + 1], lkey[1]);
    }
    __syncthreads();

    // ---- sort candidates descending by S ----
    if (tid < NCAND) {
        unsigned long long mykey = s_cand[tid];
        int rank = 0;
        for (int j = 0; j < NCAND; ++j) rank += (s_cand[j] > mykey);
        s_p[rank] = (int)(mykey & 8191ULL);
    }
    __syncthreads();

    // ---- stage all 16 candidate patches ----
    for (int i = tid; i < NCAND * 512; i += NT) {
        int k = i >> 9, idx = i & 511;
        int p = s_p[k], t = p >> 4, f = p & 15;
        xpatch[k * 512 + idx] = tile[(t + (idx >> 4)) * TP + f + (idx & 15)];
    }
    __syncthreads();

    // ---- per-warp probes: 4 channels/warp, W loaded once, no CTA barriers ----
    const float4* Ws4 = (const float4*)Wsec;
    #pragma unroll
    for (int j = 0; j < 4; ++j) {
        int c = wid * 4 + j;
        const float4* Wc = Ws4 + (size_t)c * 128;
        float4 w0 = Wc[lane], w1 = Wc[lane+32], w2 = Wc[lane+64], w3 = Wc[lane+96];
        const float4* xp = (const float4*)xpatch;
        float4 x0 = xp[lane], x1 = xp[lane+32], x2 = xp[lane+64], x3 = xp[lane+96];
        float a = 0.f;
        a = fmaf(w0.x, x0.x, a); a = fmaf(w0.y, x0.y, a); a = fmaf(w0.z, x0.z, a); a = fmaf(w0.w, x0.w, a);
        a = fmaf(w1.x, x1.x, a); a = fmaf(w1.y, x1.y, a); a = fmaf(w1.z, x1.z, a); a = fmaf(w1.w, x1.w, a);
        a = fmaf(w2.x, x2.x, a); a = fmaf(w2.y, x2.y, a); a = fmaf(w2.z, x2.z, a); a = fmaf(w2.w, x2.w, a);
        a = fmaf(w3.x, x3.x, a); a = fmaf(w3.y, x3.y, a); a = fmaf(w3.z, x3.z, a); a = fmaf(w3.w, x3.w, a);
        #pragma unroll
        for (int d = 16; d; d >>= 1) a += __shfl_xor_sync(~0u, a, d);
        bool fired = (a >= THR);
        for (int k = 1; k < NCAND && !fired; k += 2) {
            int k2 = (k + 1 < NCAND) ? k + 1 : k;
            const float4* xa = (const float4*)(xpatch + k  * 512);
            const float4* xb = (const float4*)(xpatch + k2 * 512);
            float a0 = 0.f, a1 = 0.f;
            float4 ya, yb;
            ya = xa[lane];    yb = xb[lane];
            a0 = fmaf(w0.x, ya.x, a0); a0 = fmaf(w0.y, ya.y, a0); a0 = fmaf(w0.z, ya.z, a0); a0 = fmaf(w0.w, ya.w, a0);
            a1 = fmaf(w0.x, yb.x, a1); a1 = fmaf(w0.y, yb.y, a1); a1 = fmaf(w0.z, yb.z, a1); a1 = fmaf(w0.w, yb.w, a1);
            ya = xa[lane+32]; yb = xb[lane+32];
            a0 = fmaf(w1.x, ya.x, a0); a0 = fmaf(w1.y, ya.y, a0); a0 = fmaf(w1.z, ya.z, a0); a0 = fmaf(w1.w, ya.w, a0);
            a1 = fmaf(w1.x, yb.x, a1); a1 = fmaf(w1.y, yb.y, a1); a1 = fmaf(w1.z, yb.z, a1); a1 = fmaf(w1.w, yb.w, a1);
            ya = xa[lane+64]; yb = xb[lane+64];
            a0 = fmaf(w2.x, ya.x, a0); a0 = fmaf(w2.y, ya.y, a0); a0 = fmaf(w2.z, ya.z, a0); a0 = fmaf(w2.w, ya.w, a0);
            a1 = fmaf(w2.x, yb.x, a1); a1 = fmaf(w2.y, yb.y, a1); a1 = fmaf(w2.z, yb.z, a1); a1 = fmaf(w2.w, yb.w, a1);
            ya = xa[lane+96]; yb = xb[lane+96];
            a0 = fmaf(w3.x, ya.x, a0); a0 = fmaf(w3.y, ya.y, a0); a0 = fmaf(w3.z, ya.z, a0); a0 = fmaf(w3.w, ya.w, a0);
            a1 = fmaf(w3.x, yb.x, a1); a1 = fmaf(w3.y, yb.y, a1); a1 = fmaf(w3.z, yb.z, a1); a1 = fmaf(w3.w, yb.w, a1);
            #pragma unroll
            for (int d = 16; d; d >>= 1) {
                a0 += __shfl_xor_sync(~0u, a0, d);
                a1 += __shfl_xor_sync(~0u, a1, d);
            }
            fired = (fmaxf(a0, a1) >= THR);
        }
        if (fired && lane == 0) atomicOr(&s_pool[c >> 5], 1u << (c & 31));
    }
    __syncthreads();

    // ================= rigorous cold path (rare) =================
    if ((s_pool[0] & s_pool[1] & s_pool[2] & s_pool[3]) != 0xffffffffu) {
        // row sumsq via warp scan (lazy)
        for (int r = wid; r < LPRE; r += 32) {
            float x = (lane < 31) ? tile[r * TP + lane] : 0.f;
            float p = x * x;
            #pragma unroll
            for (int d = 1; d < 32; d <<= 1) {
                float v = __shfl_up_sync(~0u, p, d);
                if (lane >= d) p += v;
            }
            float phi = __shfl_down_sync(~0u, p, 15);
            float plo = __shfl_up_sync(~0u, p, 1);
            if (lane < 16) Rt2[lane * RTP + r] = phi - (lane ? plo : 0.f);
        }
        __syncthreads();
        if (tid < 800) {
            int f = tid & 15, t0 = (tid >> 4) * 8;
            const float* Rf2 = Rt2 + f * RTP;
            float a2 = 0.f;
            for (int k = 0; k < 32; ++k) a2 += Rf2[t0 + k];
            float lsig = 0.f;
            #pragma unroll
            for (int t = t0; t < t0 + 8; ++t) {
                int p = t*16 + f;
                float S = Sarr[p];
                float var = fmaxf(a2 - S*S*(1.0f/512.0f), 0.f);
                Varr[p] = var;
                lsig = fmaxf(lsig, var);
                if (t <= 398) a2 += Rf2[t + 32] - Rf2[t];
            }
            atomicMax(&s_sig_i, __float_as_int(lsig));
        }
        if (tid < NC && !((s_pool[tid >> 5] >> (tid & 31)) & 1u))
            s_rem[atomicAdd(&s_rcnt, 1)] = tid;
        __syncthreads();

        const float Smax   = Sarr[s_p[0]];
        const float sigMax = sqrtf(__int_as_float(s_sig_i));
        const int   rb     = lane >> 4;
        const int   cofs   = lane & 15;

        for (;;) {
            int ri;
            if (lane == 0) ri = atomicAdd(&s_qhead, 1);
            ri = __shfl_sync(~0u, ri, 0);
            if (ri >= s_rcnt) break;
            const int cc = s_rem[ri];
            const float* Wr = Wsec + (size_t)cc * 512;
            float wv[16];
            #pragma unroll
            for (int i = 0; i < 16; ++i) wv[i] = Wr[lane + 32*i];
            float ws = 0.f, wq = 0.f;
            #pragma unroll
            for (int i = 0; i < 16; ++i) { ws += wv[i]; wq += wv[i]*wv[i]; }
            #pragma unroll
            for (int d = 16; d; d >>= 1) {
                ws += __shfl_xor_sync(~0u, ws, d);
                wq += __shfl_xor_sync(~0u, wq, d);
            }
            const float cw  = ws;
            const float cb2 = fmaxf(wq - ws*ws*(1.0f/512.0f), 0.f);
            if (cw * Smax * (1.0f/512.0f) + sqrtf(cb2) * sigMax < THR - MARGIN)
                continue;
            int fired = 0;
            for (int p0 = 0; p0 < NPOT && !fired; p0 += 32) {
                int p = p0 + lane;
                float S   = Sarr[p];
                float var = Varr[p];
                float base = cw * S * (1.0f/512.0f);
                float d1 = base - (THR + MARGIN);
                float d2 = (THR - MARGIN) - base;
                bool fl  = (d1 >= 0.f) && (d1*d1 >= cb2*var);
                bool amb = !fl && ((d2 <= 0.f) || (d2*d2 <= cb2*var));
                if (__ballot_sync(~0u, fl)) fired = 1;
                unsigned am = __ballot_sync(~0u, amb);
                while (am && !fired) {
                    int l0 = __ffs(am) - 1; am &= am - 1;
                    int pp = __shfl_sync(~0u, p, l0);
                    int t = pp >> 4, f = pp & 15;
                    const float* xr = tile + (t + rb) * TP + f + cofs;
                    float a = 0.f;
                    #pragma unroll
                    for (int i = 0; i < 16; ++i) a = fmaf(wv[i], xr[66*i], a);
                    #pragma unroll
                    for (int d = 16; d; d >>= 1) a += __shfl_xor_sync(~0u, a, d);
                    if (a >= THR) fired = 1;
                }
            }
            if (fired && lane == 0) atomicOr(&s_pool[cc >> 5], 1u << (cc & 31));
        }
        __syncthreads();
    }

    if (tid < 4)
        g_poolw[(s * NFW + fwin) * 4 + tid] = s_pool[tid];

    // ---- fused winner reduction (last CTA) ----
    __threadfence();
    __syncthreads();
    if (tid == 0) s_last = (atomicAdd(&g_done, 1u) == gridDim.x - 1u);
    __syncthreads();
    if (!s_last) return;
    __threadfence();

    if (tid == 0) { s_any = 0; s_key0 = -1; s_key1 = -1; }
    __syncthreads();

    int lk0 = -1, lk1 = -1, localany = 0;
    for (int cell = tid; cell < NC * NFW; cell += NT) {
        int cc = cell / NFW, f = cell % NFW;
        int wword = cc >> 5, wbit = cc & 31;
        unsigned mask = 0; int cnt = 0;
        #pragma unroll
        for (int ss = 0; ss < NS; ++ss) {
            int b = (int)((g_poolw[(ss * NFW + f) * 4 + wword] >> wbit) & 1u);
            mask |= (unsigned)b << ss; cnt += b;
        }
        int e = 8 - cnt; e = e < 0 ? 0 : (e > 7 ? 7 : e);
        int val = (int)((mask >> e) & 1u);
        if (cnt > 0 && val > 0) localany = 1;
        int k0 = ((cnt * val)       << 11) | (2047 - cell);
        int k1 = ((cnt * (val + 8)) << 11) | (2047 - cell);
        if (k0 > lk0) lk0 = k0;
        if (k1 > lk1) lk1 = k1;
    }
    #pragma unroll
    for (int d = 16; d; d >>= 1) {
        lk0 = max(lk0, __shfl_xor_sync(~0u, lk0, d));
        lk1 = max(lk1, __shfl_xor_sync(~0u, lk1, d));
        localany |= __shfl_xor_sync(~0u, localany, d);
    }
    if (lane == 0) {
        atomicMax(&s_key0, lk0);
        atomicMax(&s_key1, lk1);
        if (localany) atomicOr(&s_any, 1);
    }
    __syncthreads();

    if (tid == 0) {
        int key = s_any ? s_key1 : s_key0;
        int total = key >> 11, cell = 2047 - (key & 2047);
        out[0] = total ? (cell / NFW) : -1;
        g_done = 0;
    }
}

extern "C" void kernel_launch(void* const* d_in, const int* in_sizes, int n_in,
                              void* d_out, int out_size)
{
    (void)n_in; (void)out_size;
    const float* X = (const float*)d_in[0];
    const float* W = (const float*)d_in[1];
    if (in_sizes[0] == NS * NC * KT * KF) { const float* t = X; X = W; W = t; }

    const size_t smem = (size_t)SMEM_F * sizeof(float);
    cudaFuncSetAttribute(spyke_kernel,
                         cudaFuncAttributeMaxDynamicSharedMemorySize, (int)smem);
    spyke_kernel<<<NS * NFW, NT, smem>>>(X, W, (int*)d_out);
}

// round 16
// speedup vs baseline: 1.1083x; 1.1083x over previous
#include <cuda_runtime.h>

#define NS 8
#define NC 128
#define KT 32
#define KF 16
#define FREQ 256
#define NFW 15
#define THR 15.0f
#define LPRE 431
#define NPOT 6400
#define MARGIN 0.05f
#define NCAND 16
#define NT 1024

#define TP 33
#define RP 17
#define RROW_OFF  14224
#define S_OFF     21552
#define X2_OFF    27952
#define RROW2_OFF 34352
#define XP_OFF    41680          /* xpatch[16][512] */
#define SMEM_F    49872          /* 199,488 bytes */

__device__ unsigned g_poolw[NS * NFW * 4];
__device__ unsigned g_done;

__global__ __launch_bounds__(NT, 1)
void spyke_kernel(const float* __restrict__ X, const float* __restrict__ W,
                  int* __restrict__ out)
{
    extern __shared__ float sm[];
    float* tile   = sm;
    float* Rrow   = sm + RROW_OFF;
    float* Sarr   = sm + S_OFF;
    float* Varr   = sm + X2_OFF;
    float* Rrow2  = sm + RROW2_OFF;
    float* xpatch = sm + XP_OFF;

    __shared__ unsigned long long s_cand[NCAND];
    __shared__ int s_p[NCAND];
    __shared__ unsigned s_pool[4];
    __shared__ int s_sig_i, s_rcnt, s_qhead, s_last, s_any, s_key0, s_key1;
    __shared__ int s_rem[NC];

    const int s = blockIdx.x / NFW, fwin = blockIdx.x % NFW;
    const int tid = threadIdx.x, sec = s * 400;
    const int lane = tid & 31, wid = tid >> 5;

    if (tid < NCAND) s_cand[tid] = 0ULL;
    if (tid < 4) s_pool[tid] = 0u;
    if (tid == 0) { s_rcnt = 0; s_sig_i = 0; s_qhead = 0; }

    const float* Wsec = W + (size_t)s * NC * 512;

    // ---- prefetch W section into L2 ----
    for (int i = tid; i < 2048; i += NT)
        asm volatile("prefetch.global.L2 [%0];" :: "l"(Wsec + i * 32));

    // ---- stage X window: float4 loads ----
    {
        const float4* X4 = (const float4*)X;
        for (int i = tid; i < LPRE * 8; i += NT) {
            int r = i >> 3, c = i & 7;
            float4 v = X4[(sec + r) * 64 + fwin * 4 + c];
            float* dst = tile + r * TP + c * 4;
            dst[0] = v.x; dst[1] = v.y; dst[2] = v.z; dst[3] = v.w;
        }
    }
    __syncthreads();

    // ---- row sliding sums over kf-window of 16 ----
    if (tid < LPRE) {
        float a = 0.f;
        #pragma unroll
        for (int c = 0; c < 16; ++c) a += tile[tid*TP + c];
        Rrow[tid*RP] = a;
        #pragma unroll 5
        for (int f = 1; f < 16; ++f) {
            a += tile[tid*TP + f + 15] - tile[tid*TP + f - 1];
            Rrow[tid*RP + f] = a;
        }
    }
    __syncthreads();

    // ---- column sliding over kt-window of 32: S + per-region argmax ----
    if (tid < 400) {
        int f = tid & 15, t0 = (tid >> 4) * 16;
        float a = 0.f;
        #pragma unroll 8
        for (int k = 0; k < 32; ++k) a += Rrow[(t0+k)*RP+f];
        unsigned long long lkey[2] = {0ULL, 0ULL};
        int reg0 = t0 / 25;
        for (int t = t0; t < t0 + 16; ++t) {
            int p = t*16 + f;
            Sarr[p] = a;
            unsigned long long key =
                ((unsigned long long)__float_as_uint(a) << 13) | (unsigned)p;
            int ri = (t / 25) - reg0;
            if (key > lkey[ri]) lkey[ri] = key;
            if (t <= 398) a += Rrow[(t+32)*RP+f] - Rrow[t*RP+f];
        }
        atomicMax(&s_cand[reg0], lkey[0]);
        if (lkey[1] && reg0 + 1 < NCAND) atomicMax(&s_cand[reg0 + 1], lkey[1]);
    }
    __syncthreads();

    // ---- stage patches; slot 0 <-> global-max region, no sort phase ----
    {
        int m = 0;
        unsigned long long best = s_cand[0];
        #pragma unroll
        for (int k = 1; k < NCAND; ++k) {
            unsigned long long v = s_cand[k];
            if (v > best) { best = v; m = k; }
        }
        if (tid < NCAND) {
            int reg = (tid == 0) ? m : ((tid == m) ? 0 : tid);
            s_p[tid] = (int)(s_cand[reg] & 8191ULL);
        }
        for (int i = tid; i < NCAND * 512; i += NT) {
            int k = i >> 9, idx = i & 511;
            int reg = (k == 0) ? m : ((k == m) ? 0 : k);
            int p = (int)(s_cand[reg] & 8191ULL);
            int t = p >> 4, f = p & 15;
            xpatch[k * 512 + idx] = tile[(t + (idx >> 4)) * TP + f + (idx & 15)];
        }
    }
    __syncthreads();

    // ---- per-warp probes: 2 channel-pairs per warp, W regs shared per pair ----
    const float4* Ws4 = (const float4*)Wsec;
    #pragma unroll
    for (int j = 0; j < 2; ++j) {
        int c0 = wid * 4 + j * 2, c1 = c0 + 1;
        const float4* W0 = Ws4 + (size_t)c0 * 128;
        const float4* W1 = Ws4 + (size_t)c1 * 128;
        float4 u0 = W0[lane], u1 = W0[lane+32], u2 = W0[lane+64], u3 = W0[lane+96];
        float4 v0 = W1[lane], v1 = W1[lane+32], v2 = W1[lane+64], v3 = W1[lane+96];
        bool f0 = false, f1 = false;
        for (int k = 0; k < NCAND && !(f0 && f1); ++k) {
            const float4* xp = (const float4*)(xpatch + k * 512);
            float a0 = 0.f, a1 = 0.f;
            float4 x;
            x = xp[lane];
            a0 = fmaf(u0.x, x.x, a0); a0 = fmaf(u0.y, x.y, a0); a0 = fmaf(u0.z, x.z, a0); a0 = fmaf(u0.w, x.w, a0);
            a1 = fmaf(v0.x, x.x, a1); a1 = fmaf(v0.y, x.y, a1); a1 = fmaf(v0.z, x.z, a1); a1 = fmaf(v0.w, x.w, a1);
            x = xp[lane+32];
            a0 = fmaf(u1.x, x.x, a0); a0 = fmaf(u1.y, x.y, a0); a0 = fmaf(u1.z, x.z, a0); a0 = fmaf(u1.w, x.w, a0);
            a1 = fmaf(v1.x, x.x, a1); a1 = fmaf(v1.y, x.y, a1); a1 = fmaf(v1.z, x.z, a1); a1 = fmaf(v1.w, x.w, a1);
            x = xp[lane+64];
            a0 = fmaf(u2.x, x.x, a0); a0 = fmaf(u2.y, x.y, a0); a0 = fmaf(u2.z, x.z, a0); a0 = fmaf(u2.w, x.w, a0);
            a1 = fmaf(v2.x, x.x, a1); a1 = fmaf(v2.y, x.y, a1); a1 = fmaf(v2.z, x.z, a1); a1 = fmaf(v2.w, x.w, a1);
            x = xp[lane+96];
            a0 = fmaf(u3.x, x.x, a0); a0 = fmaf(u3.y, x.y, a0); a0 = fmaf(u3.z, x.z, a0); a0 = fmaf(u3.w, x.w, a0);
            a1 = fmaf(v3.x, x.x, a1); a1 = fmaf(v3.y, x.y, a1); a1 = fmaf(v3.z, x.z, a1); a1 = fmaf(v3.w, x.w, a1);
            #pragma unroll
            for (int d = 16; d; d >>= 1) {
                a0 += __shfl_xor_sync(~0u, a0, d);
                a1 += __shfl_xor_sync(~0u, a1, d);
            }
            f0 |= (a0 >= THR);
            f1 |= (a1 >= THR);
        }
        if (lane == 0) {
            unsigned bits = (f0 ? (1u << (c0 & 31)) : 0u) | (f1 ? (1u << (c1 & 31)) : 0u);
            if (bits) atomicOr(&s_pool[c0 >> 5], bits);
        }
    }
    __syncthreads();

    // ================= rigorous cold path (rare) =================
    if ((s_pool[0] & s_pool[1] & s_pool[2] & s_pool[3]) != 0xffffffffu) {
        if (tid < LPRE) {
            float a2 = 0.f;
            #pragma unroll
            for (int c = 0; c < 16; ++c) { float x = tile[tid*TP + c]; a2 += x*x; }
            Rrow2[tid*RP] = a2;
            for (int f = 1; f < 16; ++f) {
                float xo = tile[tid*TP + f - 1], xn = tile[tid*TP + f + 15];
                a2 += xn*xn - xo*xo;
                Rrow2[tid*RP + f] = a2;
            }
        }
        __syncthreads();
        if (tid < 400) {
            int f = tid & 15, t0 = (tid >> 4) * 16;
            float a2 = 0.f;
            for (int k = 0; k < 32; ++k) a2 += Rrow2[(t0+k)*RP+f];
            float lsig = 0.f;
            for (int t = t0; t < t0 + 16; ++t) {
                int p = t*16 + f;
                float S = Sarr[p];
                float var = fmaxf(a2 - S*S*(1.0f/512.0f), 0.f);
                Varr[p] = var;
                lsig = fmaxf(lsig, var);
                if (t <= 398) a2 += Rrow2[(t+32)*RP+f] - Rrow2[t*RP+f];
            }
            atomicMax(&s_sig_i, __float_as_int(lsig));
        }
        if (tid < NC && !((s_pool[tid >> 5] >> (tid & 31)) & 1u))
            s_rem[atomicAdd(&s_rcnt, 1)] = tid;
        __syncthreads();

        const float Smax   = Sarr[s_p[0]];
        const float sigMax = sqrtf(__int_as_float(s_sig_i));
        const int   rb     = lane >> 4;
        const int   cofs   = lane & 15;

        for (;;) {
            int ri;
            if (lane == 0) ri = atomicAdd(&s_qhead, 1);
            ri = __shfl_sync(~0u, ri, 0);
            if (ri >= s_rcnt) break;
            const int cc = s_rem[ri];
            const float* Wr = Wsec + (size_t)cc * 512;
            float wv[16];
            #pragma unroll
            for (int i = 0; i < 16; ++i) wv[i] = Wr[lane + 32*i];
            float ws = 0.f, wq = 0.f;
            #pragma unroll
            for (int i = 0; i < 16; ++i) { ws += wv[i]; wq += wv[i]*wv[i]; }
            #pragma unroll
            for (int d = 16; d; d >>= 1) {
                ws += __shfl_xor_sync(~0u, ws, d);
                wq += __shfl_xor_sync(~0u, wq, d);
            }
            const float cw  = ws;
            const float cb2 = fmaxf(wq - ws*ws*(1.0f/512.0f), 0.f);
            if (cw * Smax * (1.0f/512.0f) + sqrtf(cb2) * sigMax < THR - MARGIN)
                continue;
            int fired = 0;
            for (int p0 = 0; p0 < NPOT && !fired; p0 += 32) {
                int p = p0 + lane;
                float S   = Sarr[p];
                float var = Varr[p];
                float base = cw * S * (1.0f/512.0f);
                float d1 = base - (THR + MARGIN);
                float d2 = (THR - MARGIN) - base;
                bool fl  = (d1 >= 0.f) && (d1*d1 >= cb2*var);
                bool amb = !fl && ((d2 <= 0.f) || (d2*d2 <= cb2*var));
                if (__ballot_sync(~0u, fl)) fired = 1;
                unsigned am = __ballot_sync(~0u, amb);
                while (am && !fired) {
                    int l0 = __ffs(am) - 1; am &= am - 1;
                    int pp = __shfl_sync(~0u, p, l0);
                    int t = pp >> 4, f = pp & 15;
                    const float* xr = tile + (t + rb) * TP + f + cofs;
                    float a = 0.f;
                    #pragma unroll
                    for (int i = 0; i < 16; ++i) a = fmaf(wv[i], xr[66*i], a);
                    #pragma unroll
                    for (int d = 16; d; d >>= 1) a += __shfl_xor_sync(~0u, a, d);
                    if (a >= THR) fired = 1;
                }
            }
            if (fired && lane == 0) atomicOr(&s_pool[cc >> 5], 1u << (cc & 31));
        }
        __syncthreads();
    }

    if (tid < 4)
        g_poolw[(s * NFW + fwin) * 4 + tid] = s_pool[tid];

    // ---- fused winner reduction (last CTA) ----
    __threadfence();
    __syncthreads();
    if (tid == 0) s_last = (atomicAdd(&g_done, 1u) == gridDim.x - 1u);
    __syncthreads();
    if (!s_last) return;
    __threadfence();

    if (tid == 0) { s_any = 0; s_key0 = -1; s_key1 = -1; }
    __syncthreads();

    int lk0 = -1, lk1 = -1, localany = 0;
    for (int cell = tid; cell < NC * NFW; cell += NT) {
        int cc = cell / NFW, f = cell % NFW;
        int wword = cc >> 5, wbit = cc & 31;
        unsigned mask = 0; int cnt = 0;
        #pragma unroll
        for (int ss = 0; ss < NS; ++ss) {
            int b = (int)((g_poolw[(ss * NFW + f) * 4 + wword] >> wbit) & 1u);
            mask |= (unsigned)b << ss; cnt += b;
        }
        int e = 8 - cnt; e = e < 0 ? 0 : (e > 7 ? 7 : e);
        int val = (int)((mask >> e) & 1u);
        if (cnt > 0 && val > 0) localany = 1;
        int k0 = ((cnt * val)       << 11) | (2047 - cell);
        int k1 = ((cnt * (val + 8)) << 11) | (2047 - cell);
        if (k0 > lk0) lk0 = k0;
        if (k1 > lk1) lk1 = k1;
    }
    #pragma unroll
    for (int d = 16; d; d >>= 1) {
        lk0 = max(lk0, __shfl_xor_sync(~0u, lk0, d));
        lk1 = max(lk1, __shfl_xor_sync(~0u, lk1, d));
        localany |= __shfl_xor_sync(~0u, localany, d);
    }
    if (lane == 0) {
        atomicMax(&s_key0, lk0);
        atomicMax(&s_key1, lk1);
        if (localany) atomicOr(&s_any, 1);
    }
    __syncthreads();

    if (tid == 0) {
        int key = s_any ? s_key1 : s_key0;
        int total = key >> 11, cell = 2047 - (key & 2047);
        out[0] = total ? (cell / NFW) : -1;
        g_done = 0;
    }
}

extern "C" void kernel_launch(void* const* d_in, const int* in_sizes, int n_in,
                              void* d_out, int out_size)
{
    (void)n_in; (void)out_size;
    const float* X = (const float*)d_in[0];
    const float* W = (const float*)d_in[1];
    if (in_sizes[0] == NS * NC * KT * KF) { const float* t = X; X = W; W = t; }

    const size_t smem = (size_t)SMEM_F * sizeof(float);
    cudaFuncSetAttribute(spyke_kernel,
                         cudaFuncAttributeMaxDynamicSharedMemorySize, (int)smem);
    spyke_kernel<<<NS * NFW, NT, smem>>>(X, W, (int*)d_out);
}

// round 17
// speedup vs baseline: 1.2429x; 1.1214x over previous
#include <cuda_runtime.h>

#define NS 8
#define NC 128
#define KT 32
#define KF 16
#define FREQ 256
#define NFW 15
#define THR 15.0f
#define LPRE 431
#define NPOT 6400
#define MARGIN 0.05f
#define NCAND 16
#define NT 1024

#define TP 33
#define RP 17
#define RROW_OFF  14224
#define S_OFF     21552
#define X2_OFF    27952
#define RROW2_OFF 34352
#define XP_OFF    41680          /* xpatch[16][512] */
#define SMEM_F    49872          /* 199,488 bytes */

__device__ unsigned g_poolw[NS * NFW * 4];
__device__ unsigned g_done;

__global__ __launch_bounds__(NT, 1)
void spyke_kernel(const float* __restrict__ X, const float* __restrict__ W,
                  int* __restrict__ out)
{
    extern __shared__ float sm[];
    float* tile   = sm;
    float* Rrow   = sm + RROW_OFF;
    float* Sarr   = sm + S_OFF;
    float* Varr   = sm + X2_OFF;
    float* Rrow2  = sm + RROW2_OFF;
    float* xpatch = sm + XP_OFF;

    __shared__ unsigned long long s_cand[NCAND];
    __shared__ int s_p[NCAND];
    __shared__ unsigned s_pool[4];
    __shared__ int s_sig_i, s_rcnt, s_qhead, s_last, s_any, s_key0, s_key1;
    __shared__ int s_rem[NC];

    const int s = blockIdx.x / NFW, fwin = blockIdx.x % NFW;
    const int tid = threadIdx.x, sec = s * 400;
    const int lane = tid & 31, wid = tid >> 5;

    if (tid < NCAND) s_cand[tid] = 0ULL;
    if (tid < 4) s_pool[tid] = 0u;
    if (tid == 0) { s_rcnt = 0; s_sig_i = 0; s_qhead = 0; }

    const float* Wsec = W + (size_t)s * NC * 512;

    // ---- prefetch W section into L2 ----
    for (int i = tid; i < 2048; i += NT)
        asm volatile("prefetch.global.L2 [%0];" :: "l"(Wsec + i * 32));

    // ---- stage X window: float4 loads ----
    {
        const float4* X4 = (const float4*)X;
        for (int i = tid; i < LPRE * 8; i += NT) {
            int r = i >> 3, c = i & 7;
            float4 v = X4[(sec + r) * 64 + fwin * 4 + c];
            float* dst = tile + r * TP + c * 4;
            dst[0] = v.x; dst[1] = v.y; dst[2] = v.z; dst[3] = v.w;
        }
    }
    __syncthreads();

    // ---- row sliding sums over kf-window of 16 ----
    if (tid < LPRE) {
        float a = 0.f;
        #pragma unroll
        for (int c = 0; c < 16; ++c) a += tile[tid*TP + c];
        Rrow[tid*RP] = a;
        #pragma unroll 5
        for (int f = 1; f < 16; ++f) {
            a += tile[tid*TP + f + 15] - tile[tid*TP + f - 1];
            Rrow[tid*RP + f] = a;
        }
    }
    __syncthreads();

    // ---- column sliding over kt-window of 32: S + per-region argmax ----
    if (tid < 400) {
        int f = tid & 15, t0 = (tid >> 4) * 16;
        float a = 0.f;
        #pragma unroll 8
        for (int k = 0; k < 32; ++k) a += Rrow[(t0+k)*RP+f];
        unsigned long long lkey[2] = {0ULL, 0ULL};
        int reg0 = t0 / 25;
        for (int t = t0; t < t0 + 16; ++t) {
            int p = t*16 + f;
            Sarr[p] = a;
            unsigned long long key =
                ((unsigned long long)__float_as_uint(a) << 13) | (unsigned)p;
            int ri = (t / 25) - reg0;
            if (key > lkey[ri]) lkey[ri] = key;
            if (t <= 398) a += Rrow[(t+32)*RP+f] - Rrow[t*RP+f];
        }
        atomicMax(&s_cand[reg0], lkey[0]);
        if (lkey[1] && reg0 + 1 < NCAND) atomicMax(&s_cand[reg0 + 1], lkey[1]);
    }
    __syncthreads();

    // ---- sort candidates descending by S (full order matters) ----
    if (tid < NCAND) {
        unsigned long long mykey = s_cand[tid];
        int rank = 0;
        for (int j = 0; j < NCAND; ++j) rank += (s_cand[j] > mykey);
        s_p[rank] = (int)(mykey & 8191ULL);
    }
    __syncthreads();

    // ---- stage all 16 candidate patches ----
    for (int i = tid; i < NCAND * 512; i += NT) {
        int k = i >> 9, idx = i & 511;
        int p = s_p[k], t = p >> 4, f = p & 15;
        xpatch[k * 512 + idx] = tile[(t + (idx >> 4)) * TP + f + (idx & 15)];
    }
    __syncthreads();

    // ---- probe phase ----
    const float4* Ws4 = (const float4*)Wsec;
    {
        // Phase A: candidate 0 for ALL 4 channels, software-pipelined.
        const float4* xp = (const float4*)xpatch;
        float4 x0 = xp[lane], x1 = xp[lane+32], x2 = xp[lane+64], x3 = xp[lane+96];
        const int cb = wid * 4;
        float acc0, acc1, acc2, acc3;
        {   // pair 0: channels cb, cb+1
            const float4* A = Ws4 + (size_t)cb * 128;
            const float4* B = Ws4 + (size_t)(cb+1) * 128;
            float4 u0 = A[lane], u1 = A[lane+32], u2 = A[lane+64], u3 = A[lane+96];
            float4 v0 = B[lane], v1 = B[lane+32], v2 = B[lane+64], v3 = B[lane+96];
            float a = 0.f, b = 0.f;
            a = fmaf(u0.x,x0.x,a); a = fmaf(u0.y,x0.y,a); a = fmaf(u0.z,x0.z,a); a = fmaf(u0.w,x0.w,a);
            b = fmaf(v0.x,x0.x,b); b = fmaf(v0.y,x0.y,b); b = fmaf(v0.z,x0.z,b); b = fmaf(v0.w,x0.w,b);
            a = fmaf(u1.x,x1.x,a); a = fmaf(u1.y,x1.y,a); a = fmaf(u1.z,x1.z,a); a = fmaf(u1.w,x1.w,a);
            b = fmaf(v1.x,x1.x,b); b = fmaf(v1.y,x1.y,b); b = fmaf(v1.z,x1.z,b); b = fmaf(v1.w,x1.w,b);
            a = fmaf(u2.x,x2.x,a); a = fmaf(u2.y,x2.y,a); a = fmaf(u2.z,x2.z,a); a = fmaf(u2.w,x2.w,a);
            b = fmaf(v2.x,x2.x,b); b = fmaf(v2.y,x2.y,b); b = fmaf(v2.z,x2.z,b); b = fmaf(v2.w,x2.w,b);
            a = fmaf(u3.x,x3.x,a); a = fmaf(u3.y,x3.y,a); a = fmaf(u3.z,x3.z,a); a = fmaf(u3.w,x3.w,a);
            b = fmaf(v3.x,x3.x,b); b = fmaf(v3.y,x3.y,b); b = fmaf(v3.z,x3.z,b); b = fmaf(v3.w,x3.w,b);
            acc0 = a; acc1 = b;
        }
        {   // pair 1: channels cb+2, cb+3
            const float4* A = Ws4 + (size_t)(cb+2) * 128;
            const float4* B = Ws4 + (size_t)(cb+3) * 128;
            float4 u0 = A[lane], u1 = A[lane+32], u2 = A[lane+64], u3 = A[lane+96];
            float4 v0 = B[lane], v1 = B[lane+32], v2 = B[lane+64], v3 = B[lane+96];
            float a = 0.f, b = 0.f;
            a = fmaf(u0.x,x0.x,a); a = fmaf(u0.y,x0.y,a); a = fmaf(u0.z,x0.z,a); a = fmaf(u0.w,x0.w,a);
            b = fmaf(v0.x,x0.x,b); b = fmaf(v0.y,x0.y,b); b = fmaf(v0.z,x0.z,b); b = fmaf(v0.w,x0.w,b);
            a = fmaf(u1.x,x1.x,a); a = fmaf(u1.y,x1.y,a); a = fmaf(u1.z,x1.z,a); a = fmaf(u1.w,x1.w,a);
            b = fmaf(v1.x,x1.x,b); b = fmaf(v1.y,x1.y,b); b = fmaf(v1.z,x1.z,b); b = fmaf(v1.w,x1.w,b);
            a = fmaf(u2.x,x2.x,a); a = fmaf(u2.y,x2.y,a); a = fmaf(u2.z,x2.z,a); a = fmaf(u2.w,x2.w,a);
            b = fmaf(v2.x,x2.x,b); b = fmaf(v2.y,x2.y,b); b = fmaf(v2.z,x2.z,b); b = fmaf(v2.w,x2.w,b);
            a = fmaf(u3.x,x3.x,a); a = fmaf(u3.y,x3.y,a); a = fmaf(u3.z,x3.z,a); a = fmaf(u3.w,x3.w,a);
            b = fmaf(v3.x,x3.x,b); b = fmaf(v3.y,x3.y,b); b = fmaf(v3.z,x3.z,b); b = fmaf(v3.w,x3.w,b);
            acc2 = a; acc3 = b;
        }
        #pragma unroll
        for (int d = 16; d; d >>= 1) {      // 4-way interleaved butterfly
            acc0 += __shfl_xor_sync(~0u, acc0, d);
            acc1 += __shfl_xor_sync(~0u, acc1, d);
            acc2 += __shfl_xor_sync(~0u, acc2, d);
            acc3 += __shfl_xor_sync(~0u, acc3, d);
        }
        unsigned unres = (acc0 < THR ? 1u : 0u) | (acc1 < THR ? 2u : 0u)
                       | (acc2 < THR ? 4u : 0u) | (acc3 < THR ? 8u : 0u);
        if (lane == 0) {
            unsigned bits = ((~unres) & 0xFu) << (cb & 31);
            if (bits) atomicOr(&s_pool[cb >> 5], bits);
        }

        // Phase B (rare): unresolved channels scan sorted candidates 1..15
        while (unres) {
            int j = __ffs(unres) - 1; unres &= unres - 1;
            int c = cb + j;
            const float4* Wc = Ws4 + (size_t)c * 128;
            float4 w0 = Wc[lane], w1 = Wc[lane+32], w2 = Wc[lane+64], w3 = Wc[lane+96];
            bool fired = false;
            for (int k = 1; k < NCAND && !fired; ++k) {
                const float4* xq = (const float4*)(xpatch + k * 512);
                float4 y;
                float a = 0.f;
                y = xq[lane];
                a = fmaf(w0.x,y.x,a); a = fmaf(w0.y,y.y,a); a = fmaf(w0.z,y.z,a); a = fmaf(w0.w,y.w,a);
                y = xq[lane+32];
                a = fmaf(w1.x,y.x,a); a = fmaf(w1.y,y.y,a); a = fmaf(w1.z,y.z,a); a = fmaf(w1.w,y.w,a);
                y = xq[lane+64];
                a = fmaf(w2.x,y.x,a); a = fmaf(w2.y,y.y,a); a = fmaf(w2.z,y.z,a); a = fmaf(w2.w,y.w,a);
                y = xq[lane+96];
                a = fmaf(w3.x,y.x,a); a = fmaf(w3.y,y.y,a); a = fmaf(w3.z,y.z,a); a = fmaf(w3.w,y.w,a);
                #pragma unroll
                for (int d = 16; d; d >>= 1) a += __shfl_xor_sync(~0u, a, d);
                fired = (a >= THR);
            }
            if (fired && lane == 0) atomicOr(&s_pool[c >> 5], 1u << (c & 31));
        }
    }
    __syncthreads();

    // ================= rigorous cold path (rare) =================
    if ((s_pool[0] & s_pool[1] & s_pool[2] & s_pool[3]) != 0xffffffffu) {
        if (tid < LPRE) {
            float a2 = 0.f;
            #pragma unroll
            for (int c = 0; c < 16; ++c) { float x = tile[tid*TP + c]; a2 += x*x; }
            Rrow2[tid*RP] = a2;
            for (int f = 1; f < 16; ++f) {
                float xo = tile[tid*TP + f - 1], xn = tile[tid*TP + f + 15];
                a2 += xn*xn - xo*xo;
                Rrow2[tid*RP + f] = a2;
            }
        }
        __syncthreads();
        if (tid < 400) {
            int f = tid & 15, t0 = (tid >> 4) * 16;
            float a2 = 0.f;
            for (int k = 0; k < 32; ++k) a2 += Rrow2[(t0+k)*RP+f];
            float lsig = 0.f;
            for (int t = t0; t < t0 + 16; ++t) {
                int p = t*16 + f;
                float S = Sarr[p];
                float var = fmaxf(a2 - S*S*(1.0f/512.0f), 0.f);
                Varr[p] = var;
                lsig = fmaxf(lsig, var);
                if (t <= 398) a2 += Rrow2[(t+32)*RP+f] - Rrow2[t*RP+f];
            }
            atomicMax(&s_sig_i, __float_as_int(lsig));
        }
        if (tid < NC && !((s_pool[tid >> 5] >> (tid & 31)) & 1u))
            s_rem[atomicAdd(&s_rcnt, 1)] = tid;
        __syncthreads();

        const float Smax   = Sarr[s_p[0]];
        const float sigMax = sqrtf(__int_as_float(s_sig_i));
        const int   rb     = lane >> 4;
        const int   cofs   = lane & 15;

        for (;;) {
            int ri;
            if (lane == 0) ri = atomicAdd(&s_qhead, 1);
            ri = __shfl_sync(~0u, ri, 0);
            if (ri >= s_rcnt) break;
            const int cc = s_rem[ri];
            const float* Wr = Wsec + (size_t)cc * 512;
            float wv[16];
            #pragma unroll
            for (int i = 0; i < 16; ++i) wv[i] = Wr[lane + 32*i];
            float ws = 0.f, wq = 0.f;
            #pragma unroll
            for (int i = 0; i < 16; ++i) { ws += wv[i]; wq += wv[i]*wv[i]; }
            #pragma unroll
            for (int d = 16; d; d >>= 1) {
                ws += __shfl_xor_sync(~0u, ws, d);
                wq += __shfl_xor_sync(~0u, wq, d);
            }
            const float cw  = ws;
            const float cb2 = fmaxf(wq - ws*ws*(1.0f/512.0f), 0.f);
            if (cw * Smax * (1.0f/512.0f) + sqrtf(cb2) * sigMax < THR - MARGIN)
                continue;
            int fired = 0;
            for (int p0 = 0; p0 < NPOT && !fired; p0 += 32) {
                int p = p0 + lane;
                float S   = Sarr[p];
                float var = Varr[p];
                float base = cw * S * (1.0f/512.0f);
                float d1 = base - (THR + MARGIN);
                float d2 = (THR - MARGIN) - base;
                bool fl  = (d1 >= 0.f) && (d1*d1 >= cb2*var);
                bool amb = !fl && ((d2 <= 0.f) || (d2*d2 <= cb2*var));
                if (__ballot_sync(~0u, fl)) fired = 1;
                unsigned am = __ballot_sync(~0u, amb);
                while (am && !fired) {
                    int l0 = __ffs(am) - 1; am &= am - 1;
                    int pp = __shfl_sync(~0u, p, l0);
                    int t = pp >> 4, f = pp & 15;
                    const float* xr = tile + (t + rb) * TP + f + cofs;
                    float a = 0.f;
                    #pragma unroll
                    for (int i = 0; i < 16; ++i) a = fmaf(wv[i], xr[66*i], a);
                    #pragma unroll
                    for (int d = 16; d; d >>= 1) a += __shfl_xor_sync(~0u, a, d);
                    if (a >= THR) fired = 1;
                }
            }
            if (fired && lane == 0) atomicOr(&s_pool[cc >> 5], 1u << (cc & 31));
        }
        __syncthreads();
    }

    if (tid < 4)
        g_poolw[(s * NFW + fwin) * 4 + tid] = s_pool[tid];

    // ---- fused winner reduction (last CTA) ----
    __threadfence();
    __syncthreads();
    if (tid == 0) s_last = (atomicAdd(&g_done, 1u) == gridDim.x - 1u);
    __syncthreads();
    if (!s_last) return;
    __threadfence();

    if (tid == 0) { s_any = 0; s_key0 = -1; s_key1 = -1; }
    __syncthreads();

    int lk0 = -1, lk1 = -1, localany = 0;
    for (int cell = tid; cell < NC * NFW; cell += NT) {
        int cc = cell / NFW, f = cell % NFW;
        int wword = cc >> 5, wbit = cc & 31;
        unsigned mask = 0; int cnt = 0;
        #pragma unroll
        for (int ss = 0; ss < NS; ++ss) {
            int b = (int)((g_poolw[(ss * NFW + f) * 4 + wword] >> wbit) & 1u);
            mask |= (unsigned)b << ss; cnt += b;
        }
        int e = 8 - cnt; e = e < 0 ? 0 : (e > 7 ? 7 : e);
        int val = (int)((mask >> e) & 1u);
        if (cnt > 0 && val > 0) localany = 1;
        int k0 = ((cnt * val)       << 11) | (2047 - cell);
        int k1 = ((cnt * (val + 8)) << 11) | (2047 - cell);
        if (k0 > lk0) lk0 = k0;
        if (k1 > lk1) lk1 = k1;
    }
    #pragma unroll
    for (int d = 16; d; d >>= 1) {
        lk0 = max(lk0, __shfl_xor_sync(~0u, lk0, d));
        lk1 = max(lk1, __shfl_xor_sync(~0u, lk1, d));
        localany |= __shfl_xor_sync(~0u, localany, d);
    }
    if (lane == 0) {
        atomicMax(&s_key0, lk0);
        atomicMax(&s_key1, lk1);
        if (localany) atomicOr(&s_any, 1);
    }
    __syncthreads();

    if (tid == 0) {
        int key = s_any ? s_key1 : s_key0;
        int total = key >> 11, cell = 2047 - (key & 2047);
        out[0] = total ? (cell / NFW) : -1;
        g_done = 0;
    }
}

extern "C" void kernel_launch(void* const* d_in, const int* in_sizes, int n_in,
                              void* d_out, int out_size)
{
    (void)n_in; (void)out_size;
    const float* X = (const float*)d_in[0];
    const float* W = (const float*)d_in[1];
    if (in_sizes[0] == NS * NC * KT * KF) { const float* t = X; X = W; W = t; }

    const size_t smem = (size_t)SMEM_F * sizeof(float);
    cudaFuncSetAttribute(spyke_kernel,
                         cudaFuncAttributeMaxDynamicSharedMemorySize, (int)smem);
    spyke_kernel<<<NS * NFW, NT, smem>>>(X, W, (int*)d_out);
}